// round 11
// baseline (speedup 1.0000x reference)
#include <cuda_runtime.h>
#include <cuda_bf16.h>
#include <cstdint>

#define MM 8192
#define DD 2048
#define NN 8192
#define TOPK 819
typedef unsigned short u16;
typedef signed char s8;

__device__ double g_partial[4096];
__device__ float  g_scale[2];
__device__ float  g_xs[MM];                      // per-row x scale
__device__ float  g_hs[MM];                      // per-row hidden scale
__device__ __align__(16) s8    g_X1[(size_t)MM * DD];
__device__ __align__(16) s8    g_X2[(size_t)MM * DD];
__device__ __align__(16) s8    g_X3[(size_t)MM * DD];
__device__ __align__(16) s8    g_Q1[(size_t)NN * DD];
__device__ __align__(16) s8    g_Q2[(size_t)DD * NN];
__device__ __align__(16) float g_Z [(size_t)MM * NN];
__device__ __align__(16) s8    g_H1[(size_t)MM * NN];
__device__ __align__(16) s8    g_H2[(size_t)MM * NN];
__device__ __align__(16) float g_XO[(size_t)MM * DD];

__device__ __forceinline__ uint32_t smem_u32(const void* p) {
    uint32_t a;
    asm("{ .reg .u64 t; cvta.to.shared.u64 t, %1; cvt.u32.u64 %0, t; }" : "=r"(a) : "l"(p));
    return a;
}
#define CP_COMMIT() asm volatile("cp.async.commit_group;" ::: "memory")
#define CP_WAIT(n)  asm volatile("cp.async.wait_group %0;" :: "n"(n) : "memory")

__device__ __forceinline__ void ldsm4(uint32_t* r, uint32_t addr) {
    asm volatile("ldmatrix.sync.aligned.m8n8.x4.shared.b16 {%0,%1,%2,%3}, [%4];"
                 : "=r"(r[0]), "=r"(r[1]), "=r"(r[2]), "=r"(r[3]) : "r"(addr));
}
__device__ __forceinline__ void imma16832(int* c, uint32_t a0, uint32_t a1,
                                          uint32_t a2, uint32_t a3,
                                          uint32_t b0, uint32_t b1) {
    asm volatile(
        "mma.sync.aligned.m16n8k32.row.col.s32.s8.s8.s32 "
        "{%0,%1,%2,%3}, {%4,%5,%6,%7}, {%8,%9}, {%0,%1,%2,%3};\n"
        : "+r"(c[0]), "+r"(c[1]), "+r"(c[2]), "+r"(c[3])
        : "r"(a0), "r"(a1), "r"(a2), "r"(a3), "r"(b0), "r"(b1));
}

// ---------------- prep ------------------------------------------------------
__global__ void k_abs_partial(const float* __restrict__ W, int which) {
    __shared__ double sd[256];
    size_t base = (size_t)blockIdx.x * 8192 + threadIdx.x;
    double s = 0.0;
#pragma unroll
    for (int i = 0; i < 32; i++) s += (double)fabsf(W[base + (size_t)i * 256]);
    sd[threadIdx.x] = s; __syncthreads();
    for (int o = 128; o > 0; o >>= 1) {
        if ((int)threadIdx.x < o) sd[threadIdx.x] += sd[threadIdx.x + o];
        __syncthreads();
    }
    if (threadIdx.x == 0) g_partial[which * 2048 + blockIdx.x] = sd[0];
}
__global__ void k_finalize_scales() {
    __shared__ double sd[256];
    for (int w = 0; w < 2; w++) {
        double s = 0.0;
        for (int i = threadIdx.x; i < 2048; i += 256) s += g_partial[w * 2048 + i];
        sd[threadIdx.x] = s; __syncthreads();
        for (int o = 128; o > 0; o >>= 1) {
            if ((int)threadIdx.x < o) sd[threadIdx.x] += sd[threadIdx.x + o];
            __syncthreads();
        }
        if (threadIdx.x == 0) g_scale[w] = (float)(sd[0] / 16777216.0);
        __syncthreads();
    }
}
__device__ __forceinline__ s8 tqi(float w, float den) {
    float t = __fdiv_rn(w, den);
    float q = fmaxf(-1.0f, fminf(1.0f, rintf(t)));
    return (s8)(int)q;
}
__global__ void k_quantw(const float4* __restrict__ Wa, const float4* __restrict__ Wb) {
    const int which = blockIdx.y;
    const float4* W = which ? Wb : Wa;
    size_t i = (size_t)blockIdx.x * blockDim.x + threadIdx.x;
    float den = g_scale[which] + 1e-8f;
    float4 w = W[i];
    char4 q;
    q.x = tqi(w.x, den); q.y = tqi(w.y, den); q.z = tqi(w.z, den); q.w = tqi(w.w, den);
    reinterpret_cast<char4*>(which ? g_Q2 : g_Q1)[i] = q;
}
__global__ void k_rowmax(const float4* __restrict__ x) {
    __shared__ float red[256];
    const int row = blockIdx.x, t = threadIdx.x;
    float4 v0 = x[(size_t)row * 512 + t];
    float4 v1 = x[(size_t)row * 512 + t + 256];
    float m = fmaxf(fmaxf(fabsf(v0.x), fabsf(v0.y)), fmaxf(fabsf(v0.z), fabsf(v0.w)));
    m = fmaxf(m, fmaxf(fmaxf(fabsf(v1.x), fabsf(v1.y)), fmaxf(fabsf(v1.z), fabsf(v1.w))));
    red[t] = m; __syncthreads();
    for (int o = 128; o > 0; o >>= 1) {
        if (t < o) red[t] = fmaxf(red[t], red[t + o]);
        __syncthreads();
    }
    if (t == 0) g_xs[row] = fmaxf(red[0], 1e-30f) / 126.0f;
}
// x -> 3 int8 limb planes: x = s*(q1 + q2/252 + q3/63504), |resid| <= s/127008
__global__ void k_xq3(const float4* __restrict__ x) {
    size_t i = (size_t)blockIdx.x * blockDim.x + threadIdx.x;   // float4 idx
    int row = (int)(i >> 9);
    float s  = g_xs[row];
    float c0 = 1.0f / s, c1 = 252.0f / s, c2 = 63504.0f / s;
    float s1 = s, s2 = s * (1.0f / 252.0f);
    float4 v = x[i];
    float f[4] = {v.x, v.y, v.z, v.w};
    char4 o1, o2, o3;
    s8* p1 = &o1.x; s8* p2 = &o2.x; s8* p3 = &o3.x;
#pragma unroll
    for (int j = 0; j < 4; j++) {
        float t1 = rintf(f[j] * c0);
        float r1 = fmaf(-t1, s1, f[j]);
        float t2 = rintf(r1 * c1);
        float r2 = fmaf(-t2, s2, r1);
        float t3 = fmaxf(-127.0f, fminf(127.0f, rintf(r2 * c2)));
        p1[j] = (s8)(int)t1; p2[j] = (s8)(int)t2; p3[j] = (s8)(int)t3;
    }
    reinterpret_cast<char4*>(g_X1)[i] = o1;
    reinterpret_cast<char4*>(g_X2)[i] = o2;
    reinterpret_cast<char4*>(g_X3)[i] = o3;
}

// ---------------- pipelined IMMA GEMM ---------------------------------------
// CTA 128x128, 16 warps (4m x 4n), warp tile 32x32, k-step 64 (int8 bytes),
// 3-stage cp.async, 80B-pitch smem rows (conflict-free ldmatrix).
// int32 accumulation is exact; limbs combined in epilogue.
template<int GID, int NLIMB>
__global__ void __launch_bounds__(512) k_gemm_imma(
    const float* __restrict__ bias, const float* __restrict__ xres) {
    constexpr int AT = 10240;                 // 128 rows * 80B
    constexpr int BT = 10240;
    constexpr int STAGE = NLIMB * AT + BT;
    constexpr int Kdim = (GID == 0) ? DD : NN;    // bytes == elements (int8)
    constexpr int Nout = (GID == 0) ? NN : DD;
    constexpr int steps = Kdim >> 6;
    constexpr float INV1 = 1.0f / 252.0f;
    constexpr float INV2 = 1.0f / 63504.0f;

    extern __shared__ char sm[];
    const uint32_t smaddr = smem_u32(sm);
    const int tid = threadIdx.x;
    const int warp = tid >> 5, lane = tid & 31;
    const int wm = warp >> 2, wn = warp & 3;
    const int tr = lane >> 2, tc = lane & 3;
    const int m0 = blockIdx.y * 128, n0 = blockIdx.x * 128;

    const s8* At[3];
    if (GID == 0) { At[0] = g_X1; At[1] = g_X2; At[2] = g_X3; }
    else          { At[0] = g_H1; At[1] = g_H2; At[2] = g_H2; }
    const s8* Bq = (GID == 0) ? g_Q1 : g_Q2;
    float* Cout = (GID == 0) ? g_Z : g_XO;
    const float* rsc = (GID == 0) ? g_xs : g_hs;

    int acc[NLIMB][2][4][4];
#pragma unroll
    for (int l = 0; l < NLIMB; l++)
#pragma unroll
        for (int a = 0; a < 2; a++)
#pragma unroll
            for (int b = 0; b < 4; b++)
#pragma unroll
                for (int c = 0; c < 4; c++) acc[l][a][b][c] = 0;

    const int lrow = tid >> 2, lcol = (tid & 3) * 16;
    const uint32_t aoff = (uint32_t)((wm * 32 + (lane & 15)) * 80 + ((lane & 16) ? 16 : 0));
    const uint32_t boff = (uint32_t)((wn * 32 + (lane & 7) + ((lane & 16) ? 8 : 0)) * 80 +
                                     ((lane & 8) ? 16 : 0));

#pragma unroll
    for (int st = 0; st < 2; st++) {
        const int kk = st * 64;
#pragma unroll
        for (int l = 0; l < NLIMB; l++) {
            uint32_t dst = smaddr + st * STAGE + l * AT + lrow * 80 + lcol;
            const s8* src = At[l] + (size_t)(m0 + lrow) * Kdim + kk + lcol;
            asm volatile("cp.async.cg.shared.global [%0], [%1], 16;" :: "r"(dst), "l"(src) : "memory");
        }
        {
            uint32_t dst = smaddr + st * STAGE + NLIMB * AT + lrow * 80 + lcol;
            const s8* src = Bq + (size_t)(n0 + lrow) * Kdim + kk + lcol;
            asm volatile("cp.async.cg.shared.global [%0], [%1], 16;" :: "r"(dst), "l"(src) : "memory");
        }
        CP_COMMIT();
    }

    for (int t = 0; t < steps; t++) {
        CP_WAIT(1);
        __syncthreads();
        if (t + 2 < steps) {
            const int st = (t + 2) % 3, kk = (t + 2) * 64;
#pragma unroll
            for (int l = 0; l < NLIMB; l++) {
                uint32_t dst = smaddr + st * STAGE + l * AT + lrow * 80 + lcol;
                const s8* src = At[l] + (size_t)(m0 + lrow) * Kdim + kk + lcol;
                asm volatile("cp.async.cg.shared.global [%0], [%1], 16;" :: "r"(dst), "l"(src) : "memory");
            }
            {
                uint32_t dst = smaddr + st * STAGE + NLIMB * AT + lrow * 80 + lcol;
                const s8* src = Bq + (size_t)(n0 + lrow) * Kdim + kk + lcol;
                asm volatile("cp.async.cg.shared.global [%0], [%1], 16;" :: "r"(dst), "l"(src) : "memory");
            }
        }
        CP_COMMIT();

        const uint32_t sstage = smaddr + (t % 3) * STAGE;
        const uint32_t sB = sstage + NLIMB * AT;
#pragma unroll
        for (int h = 0; h < 2; h++) {
            uint32_t breg[2][4];
            ldsm4(breg[0], sB + boff + h * 32);
            ldsm4(breg[1], sB + boff + 1280 + h * 32);
#pragma unroll
            for (int l = 0; l < NLIMB; l++) {
                uint32_t areg[2][4];
                ldsm4(areg[0], sstage + l * AT + aoff + h * 32);
                ldsm4(areg[1], sstage + l * AT + aoff + 1280 + h * 32);
#pragma unroll
                for (int mt = 0; mt < 2; mt++)
#pragma unroll
                    for (int nt = 0; nt < 4; nt++)
                        imma16832(acc[l][mt][nt],
                                  areg[mt][0], areg[mt][1], areg[mt][2], areg[mt][3],
                                  breg[nt >> 1][(nt & 1) * 2], breg[nt >> 1][(nt & 1) * 2 + 1]);
            }
        }
    }

    const float sc = g_scale[GID];
#pragma unroll
    for (int mt = 0; mt < 2; mt++) {
        int r = m0 + wm * 32 + mt * 16 + tr;
        float sa = rsc[r] * sc, sb = rsc[r + 8] * sc;
#pragma unroll
        for (int nt = 0; nt < 4; nt++) {
            int n = n0 + wn * 32 + nt * 8 + tc * 2;
            float2 bs = *reinterpret_cast<const float2*>(bias + n);
            float cf[4];
#pragma unroll
            for (int e = 0; e < 4; e++) {
                float v = (float)acc[0][mt][nt][e];
                if (NLIMB >= 2) v += (float)acc[1][mt][nt][e] * INV1;
                if (NLIMB >= 3) v += (float)acc[2][mt][nt][e] * INV2;
                cf[e] = v;
            }
            float2 o0 = make_float2(fmaf(sa, cf[0], bs.x), fmaf(sa, cf[1], bs.y));
            float2 o1 = make_float2(fmaf(sb, cf[2], bs.x), fmaf(sb, cf[3], bs.y));
            if (GID == 1) {
                float2 x0 = *reinterpret_cast<const float2*>(xres + (size_t)r * Nout + n);
                float2 x1 = *reinterpret_cast<const float2*>(xres + (size_t)(r + 8) * Nout + n);
                o0.x += x0.x; o0.y += x0.y; o1.x += x1.x; o1.y += x1.y;
            }
            *reinterpret_cast<float2*>(Cout + (size_t)r * Nout + n)       = o0;
            *reinterpret_cast<float2*>(Cout + (size_t)(r + 8) * Nout + n) = o1;
        }
    }
}

// ------- exact per-row kth-largest + fused hidden (2 int8 limbs) ----------
__device__ __forceinline__ uint32_t fmap(float f) {
    uint32_t b = __float_as_uint(f);
    return (b & 0x80000000u) ? ~b : (b | 0x80000000u);
}
__device__ __forceinline__ float funmap(uint32_t u) {
    uint32_t bits = (u & 0x80000000u) ? (u ^ 0x80000000u) : ~u;
    return __uint_as_float(bits);
}
__global__ void k_topk_hidden() {
    __shared__ uint32_t srow[NN];
    __shared__ uint32_t hist[256];
    __shared__ uint32_t redmax[256];
    __shared__ uint32_t s_prefix, s_kk;
    const int row = blockIdx.x, tid = threadIdx.x;

    const uint4* zp = reinterpret_cast<const uint4*>(g_Z + (size_t)row * NN);
    uint32_t um = 0;
    for (int i = tid; i < NN / 4; i += 256) {
        uint4 v = zp[i];
        uint32_t u0 = fmap(__uint_as_float(v.x));
        uint32_t u1 = fmap(__uint_as_float(v.y));
        uint32_t u2 = fmap(__uint_as_float(v.z));
        uint32_t u3 = fmap(__uint_as_float(v.w));
        srow[i * 4 + 0] = u0; srow[i * 4 + 1] = u1;
        srow[i * 4 + 2] = u2; srow[i * 4 + 3] = u3;
        um = max(um, max(max(u0, u1), max(u2, u3)));
    }
    redmax[tid] = um;
    if (tid == 0) { s_prefix = 0u; s_kk = TOPK; }
    __syncthreads();
    for (int o = 128; o > 0; o >>= 1) {
        if (tid < o) redmax[tid] = max(redmax[tid], redmax[tid + o]);
        __syncthreads();
    }
    const float hmax = fmaxf(funmap(redmax[0]), 1e-20f);

    uint32_t maskhi = 0u;
    for (int b = 3; b >= 0; b--) {
        hist[tid] = 0u;
        __syncthreads();
        const uint32_t pref = s_prefix;
        const int sh = 8 * b;
        for (int i = tid; i < NN; i += 256) {
            uint32_t u = srow[i];
            if ((u & maskhi) == pref) atomicAdd(&hist[(u >> sh) & 0xFF], 1u);
        }
        __syncthreads();
        if (tid == 0) {
            uint32_t cum = 0, kk = s_kk; int sel = 0;
            for (int v = 255; v >= 0; v--) {
                uint32_t c = hist[v];
                if (cum + c >= kk) { sel = v; s_kk = kk - cum; break; }
                cum += c;
            }
            s_prefix = pref | ((uint32_t)sel << sh);
        }
        __syncthreads();
        maskhi |= (0xFFu << (8 * b));
    }
    const float th = funmap(s_prefix);

    const float shs = hmax / 126.0f;
    const float c0 = 126.0f / hmax, c1 = 252.0f / shs;
    if (tid == 0) g_hs[row] = shs;
    s8* h1 = g_H1 + (size_t)row * NN;
    s8* h2 = g_H2 + (size_t)row * NN;
    for (int i = tid; i < NN / 4; i += 256) {
        char4 o1, o2;
        s8* p1 = &o1.x; s8* p2 = &o2.x;
#pragma unroll
        for (int j = 0; j < 4; j++) {
            float z = funmap(srow[i * 4 + j]);
            float h = (z >= th && z > 0.0f) ? z : 0.0f;
            float t1 = rintf(h * c0);
            float r1 = fmaf(-t1, shs, h);
            float t2 = fmaxf(-127.0f, fminf(127.0f, rintf(r1 * c1)));
            p1[j] = (s8)(int)t1; p2[j] = (s8)(int)t2;
        }
        reinterpret_cast<char4*>(h1)[i] = o1;
        reinterpret_cast<char4*>(h2)[i] = o2;
    }
}

__global__ void k_ln(const float* __restrict__ gamma, const float* __restrict__ beta,
                     float* __restrict__ out) {
    __shared__ float ssum[256], ssq[256];
    const int row = blockIdx.x, t = threadIdx.x;
    const float4* xp = reinterpret_cast<const float4*>(g_XO + (size_t)row * DD);
    float4 v0 = xp[t], v1 = xp[t + 256];
    float s = v0.x + v0.y + v0.z + v0.w + v1.x + v1.y + v1.z + v1.w;
    float q = v0.x * v0.x + v0.y * v0.y + v0.z * v0.z + v0.w * v0.w +
              v1.x * v1.x + v1.y * v1.y + v1.z * v1.z + v1.w * v1.w;
    ssum[t] = s; ssq[t] = q; __syncthreads();
    for (int o = 128; o > 0; o >>= 1) {
        if (t < o) { ssum[t] += ssum[t + o]; ssq[t] += ssq[t + o]; }
        __syncthreads();
    }
    float mu  = ssum[0] * (1.0f / DD);
    float var = ssq[0] * (1.0f / DD) - mu * mu;
    float rs  = rsqrtf(var + 1e-5f);
    const float4* gp = reinterpret_cast<const float4*>(gamma);
    const float4* bp = reinterpret_cast<const float4*>(beta);
    float4 g0 = gp[t], g1 = gp[t + 256];
    float4 b0 = bp[t], b1 = bp[t + 256];
    float4 o0, o1;
    o0.x = (v0.x - mu) * rs * g0.x + b0.x; o0.y = (v0.y - mu) * rs * g0.y + b0.y;
    o0.z = (v0.z - mu) * rs * g0.z + b0.z; o0.w = (v0.w - mu) * rs * g0.w + b0.w;
    o1.x = (v1.x - mu) * rs * g1.x + b1.x; o1.y = (v1.y - mu) * rs * g1.y + b1.y;
    o1.z = (v1.z - mu) * rs * g1.z + b1.z; o1.w = (v1.w - mu) * rs * g1.w + b1.w;
    float4* op = reinterpret_cast<float4*>(out + (size_t)row * DD);
    op[t] = o0; op[t + 256] = o1;
}

// ---------------- launcher --------------------------------------------------
extern "C" void kernel_launch(void* const* d_in, const int* in_sizes, int n_in,
                              void* d_out, int out_size) {
    (void)in_sizes; (void)n_in; (void)out_size;
    const float* x     = (const float*)d_in[0];
    const float* W_syn = (const float*)d_in[1];
    const float* b_syn = (const float*)d_in[2];
    const float* W_out = (const float*)d_in[3];
    const float* b_out = (const float*)d_in[4];
    const float* gamma = (const float*)d_in[5];
    const float* beta  = (const float*)d_in[6];
    float* out = (float*)d_out;

    const int SM1 = 3 * (3 * 10240 + 10240);   // 122880 B
    const int SM2 = 3 * (2 * 10240 + 10240);   //  92160 B
    cudaFuncSetAttribute(k_gemm_imma<0, 3>, cudaFuncAttributeMaxDynamicSharedMemorySize, SM1);
    cudaFuncSetAttribute(k_gemm_imma<1, 2>, cudaFuncAttributeMaxDynamicSharedMemorySize, SM2);

    k_abs_partial<<<2048, 256>>>(W_syn, 0);
    k_abs_partial<<<2048, 256>>>(W_out, 1);
    k_finalize_scales<<<1, 256>>>();
    k_quantw<<<dim3(16384, 2), 256>>>((const float4*)W_syn, (const float4*)W_out);
    k_rowmax<<<MM, 256>>>((const float4*)x);
    k_xq3<<<16384, 256>>>((const float4*)x);
    k_gemm_imma<0, 3><<<dim3(64, 64), 512, SM1>>>(b_syn, nullptr);
    k_topk_hidden<<<MM, 256>>>();
    k_gemm_imma<1, 2><<<dim3(16, 64), 512, SM2>>>(b_out, x);
    k_ln<<<MM, 256>>>(gamma, beta, out);
}

// round 12
// speedup vs baseline: 2.5998x; 2.5998x over previous
#include <cuda_runtime.h>
#include <cuda_bf16.h>
#include <cstdint>

#define MM 8192
#define DD 2048
#define NN 8192
#define TOPK 819
#define BANDCAP 192
typedef unsigned short u16;

__device__ double g_partial[4096];
__device__ float  g_scale[2];
__device__ __align__(16) u16   g_X1[(size_t)MM * DD];
__device__ __align__(16) u16   g_X2[(size_t)MM * DD];
__device__ __align__(16) u16   g_Q1[(size_t)NN * DD];
__device__ __align__(16) u16   g_Q2[(size_t)DD * NN];
__device__ __align__(16) float g_Z [(size_t)MM * NN];
__device__ __align__(16) u16   g_H1[(size_t)MM * NN];
__device__ __align__(16) float g_XO[(size_t)MM * DD];

__device__ __forceinline__ uint32_t smem_u32(const void* p) {
    uint32_t a;
    asm("{ .reg .u64 t; cvta.to.shared.u64 t, %1; cvt.u32.u64 %0, t; }" : "=r"(a) : "l"(p));
    return a;
}
#define CP_COMMIT() asm volatile("cp.async.commit_group;" ::: "memory")
#define CP_WAIT(n)  asm volatile("cp.async.wait_group %0;" :: "n"(n) : "memory")

__device__ __forceinline__ void ldsm4(uint32_t* r, uint32_t addr) {
    asm volatile("ldmatrix.sync.aligned.m8n8.x4.shared.b16 {%0,%1,%2,%3}, [%4];"
                 : "=r"(r[0]), "=r"(r[1]), "=r"(r[2]), "=r"(r[3]) : "r"(addr));
}
__device__ __forceinline__ void mma16816(float* c, uint32_t a0, uint32_t a1,
                                         uint32_t a2, uint32_t a3,
                                         uint32_t b0, uint32_t b1) {
    asm volatile(
        "mma.sync.aligned.m16n8k16.row.col.f32.bf16.bf16.f32 "
        "{%0,%1,%2,%3}, {%4,%5,%6,%7}, {%8,%9}, {%0,%1,%2,%3};\n"
        : "+f"(c[0]), "+f"(c[1]), "+f"(c[2]), "+f"(c[3])
        : "r"(a0), "r"(a1), "r"(a2), "r"(a3), "r"(b0), "r"(b1));
}

// ---------------- prep (exactly 3 launches before GEMM1) -------------------
__global__ void k_abs2(const float* __restrict__ Wa, const float* __restrict__ Wb) {
    __shared__ double sd[256];
    const int which = blockIdx.y;
    const float* W = which ? Wb : Wa;
    size_t base = (size_t)blockIdx.x * 8192 + threadIdx.x;
    double s = 0.0;
#pragma unroll
    for (int i = 0; i < 32; i++) s += (double)fabsf(W[base + (size_t)i * 256]);
    sd[threadIdx.x] = s; __syncthreads();
    for (int o = 128; o > 0; o >>= 1) {
        if ((int)threadIdx.x < o) sd[threadIdx.x] += sd[threadIdx.x + o];
        __syncthreads();
    }
    if (threadIdx.x == 0) g_partial[which * 2048 + blockIdx.x] = sd[0];
}
__global__ void k_finalize_scales() {
    __shared__ double sd[256];
    for (int w = 0; w < 2; w++) {
        double s = 0.0;
        for (int i = threadIdx.x; i < 2048; i += 256) s += g_partial[w * 2048 + i];
        sd[threadIdx.x] = s; __syncthreads();
        for (int o = 128; o > 0; o >>= 1) {
            if ((int)threadIdx.x < o) sd[threadIdx.x] += sd[threadIdx.x + o];
            __syncthreads();
        }
        if (threadIdx.x == 0) g_scale[w] = (float)(sd[0] / 16777216.0);
        __syncthreads();
    }
}
__device__ __forceinline__ u16 tq1(float w, float den) {
    float t = __fdiv_rn(w, den);
    float q = fmaxf(-1.0f, fminf(1.0f, rintf(t)));
    return __bfloat16_as_ushort(__float2bfloat16_rn(q));
}
// one launch: quant W_syn (blocks 0..16383), quant W_out (16384..32767),
// x -> 2 bf16 limb planes (32768..49151)
__global__ void k_prep(const float4* __restrict__ Wa, const float4* __restrict__ Wb,
                       const float4* __restrict__ x) {
    const int part = blockIdx.x >> 14;
    size_t i = ((size_t)(blockIdx.x & 16383)) * 256 + threadIdx.x;
    if (part < 2) {
        const float4* W = part ? Wb : Wa;
        float den = g_scale[part] + 1e-8f;
        float4 w = W[i];
        ushort4 q;
        q.x = tq1(w.x, den); q.y = tq1(w.y, den); q.z = tq1(w.z, den); q.w = tq1(w.w, den);
        reinterpret_cast<ushort4*>(part ? g_Q2 : g_Q1)[i] = q;
    } else {
        float4 v = x[i];
        float f[4] = {v.x, v.y, v.z, v.w};
        ushort4 p1, p2;
        u16* a1 = &p1.x; u16* a2 = &p2.x;
#pragma unroll
        for (int j = 0; j < 4; j++) {
            __nv_bfloat16 b1 = __float2bfloat16_rn(f[j]);
            float r1 = f[j] - __bfloat162float(b1);
            a1[j] = __bfloat16_as_ushort(b1);
            a2[j] = __bfloat16_as_ushort(__float2bfloat16_rn(r1));
        }
        reinterpret_cast<ushort4*>(g_X1)[i] = p1;
        reinterpret_cast<ushort4*>(g_X2)[i] = p2;
    }
}

// ---------------- pipelined HMMA GEMM, k-step 64 ----------------------------
// CTA 128(m) x 256(n), 8 warps (2m x 4n), warp tile 64x64, k-step 64,
// 3-stage cp.async. smem rows 128B data + 16B pad = 144B pitch
// (16x9 -> ldmatrix 8-row phases hit 8 distinct banks: 9r mod 8 = r mod 8).
template<int GID, int NLIMB>
__global__ void __launch_bounds__(256) k_gemm_hmma(
    const float* __restrict__ bias, const float* __restrict__ xres) {
    constexpr int AT = 128 * 144;             // 18432
    constexpr int BT = 256 * 144;             // 36864
    constexpr int STAGE = NLIMB * AT + BT;
    constexpr int Kdim = (GID == 0) ? DD : NN;
    constexpr int Nout = (GID == 0) ? NN : DD;
    constexpr int steps = Kdim >> 6;

    extern __shared__ char sm[];
    const uint32_t smaddr = smem_u32(sm);
    const int tid = threadIdx.x;
    const int warp = tid >> 5, lane = tid & 31;
    const int wm = warp >> 2, wn = warp & 3;
    const int tr = lane >> 2, tc = lane & 3;
    const int m0 = blockIdx.y * 128, n0 = blockIdx.x * 256;

    const u16* At[2];
    if (GID == 0) { At[0] = g_X1; At[1] = g_X2; }
    else          { At[0] = g_H1; At[1] = g_H1; }
    const u16* Bq = (GID == 0) ? g_Q1 : g_Q2;
    float* Cout = (GID == 0) ? g_Z : g_XO;

    float acc[4][8][4];
#pragma unroll
    for (int a = 0; a < 4; a++)
#pragma unroll
        for (int b = 0; b < 8; b++)
#pragma unroll
            for (int c = 0; c < 4; c++) acc[a][b][c] = 0.0f;

    const uint32_t aoff = (uint32_t)((wm * 64 + (lane & 15)) * 144 + ((lane & 16) ? 16 : 0));
    const uint32_t boff = (uint32_t)((wn * 64 + (lane & 7) + ((lane & 16) ? 8 : 0)) * 144 +
                                     ((lane & 8) ? 16 : 0));

    // loader macro body: one full stage = NLIMB A tiles (128x128B) + B (256x128B)
#define LOAD_STAGE(stbuf, kkelem)                                                     \
    do {                                                                              \
        _Pragma("unroll")                                                             \
        for (int l = 0; l < NLIMB; l++) {                                             \
            _Pragma("unroll")                                                         \
            for (int j = 0; j < 4; j++) {                                             \
                int c = tid + 256 * j;                                                \
                int row = c >> 3, col = (c & 7) * 16;                                 \
                uint32_t dst = smaddr + (stbuf) * STAGE + l * AT + row * 144 + col;   \
                const char* src = (const char*)(At[l] + (size_t)(m0 + row) * Kdim + (kkelem)) + col; \
                asm volatile("cp.async.cg.shared.global [%0], [%1], 16;" :: "r"(dst), "l"(src) : "memory"); \
            }                                                                         \
        }                                                                             \
        _Pragma("unroll")                                                             \
        for (int j = 0; j < 8; j++) {                                                 \
            int c = tid + 256 * j;                                                    \
            int row = c >> 3, col = (c & 7) * 16;                                     \
            uint32_t dst = smaddr + (stbuf) * STAGE + NLIMB * AT + row * 144 + col;   \
            const char* src = (const char*)(Bq + (size_t)(n0 + row) * Kdim + (kkelem)) + col; \
            asm volatile("cp.async.cg.shared.global [%0], [%1], 16;" :: "r"(dst), "l"(src) : "memory"); \
        }                                                                             \
    } while (0)

#pragma unroll
    for (int st = 0; st < 2; st++) {
        LOAD_STAGE(st, st * 64);
        CP_COMMIT();
    }

    for (int t = 0; t < steps; t++) {
        CP_WAIT(1);
        __syncthreads();
        if (t + 2 < steps) {
            const int st = (t + 2) % 3;
            LOAD_STAGE(st, (t + 2) * 64);
        }
        CP_COMMIT();

        const uint32_t sstage = smaddr + (t % 3) * STAGE;
        const uint32_t sB = sstage + NLIMB * AT;
#pragma unroll
        for (int h = 0; h < 4; h++) {
            uint32_t breg[4][4];
#pragma unroll
            for (int nb = 0; nb < 4; nb++)
                ldsm4(breg[nb], sB + boff + nb * 2304 + h * 32);
#pragma unroll
            for (int l = 0; l < NLIMB; l++) {
                uint32_t areg[4][4];
#pragma unroll
                for (int mt = 0; mt < 4; mt++)
                    ldsm4(areg[mt], sstage + l * AT + aoff + mt * 2304 + h * 32);
#pragma unroll
                for (int mt = 0; mt < 4; mt++)
#pragma unroll
                    for (int nt = 0; nt < 8; nt++)
                        mma16816(acc[mt][nt], areg[mt][0], areg[mt][1], areg[mt][2], areg[mt][3],
                                 breg[nt >> 1][(nt & 1) * 2], breg[nt >> 1][(nt & 1) * 2 + 1]);
            }
        }
    }
#undef LOAD_STAGE

    const float sc = g_scale[GID];
#pragma unroll
    for (int mt = 0; mt < 4; mt++) {
        int r = m0 + wm * 64 + mt * 16 + tr;
#pragma unroll
        for (int nt = 0; nt < 8; nt++) {
            int n = n0 + wn * 64 + nt * 8 + tc * 2;
            float2 bs = *reinterpret_cast<const float2*>(bias + n);
            float2 o0 = make_float2(fmaf(acc[mt][nt][0], sc, bs.x),
                                    fmaf(acc[mt][nt][1], sc, bs.y));
            float2 o1 = make_float2(fmaf(acc[mt][nt][2], sc, bs.x),
                                    fmaf(acc[mt][nt][3], sc, bs.y));
            if (GID == 1) {
                float2 x0 = *reinterpret_cast<const float2*>(xres + (size_t)r * Nout + n);
                float2 x1 = *reinterpret_cast<const float2*>(xres + (size_t)(r + 8) * Nout + n);
                o0.x += x0.x; o0.y += x0.y; o1.x += x1.x; o1.y += x1.y;
            }
            *reinterpret_cast<float2*>(Cout + (size_t)r * Nout + n)       = o0;
            *reinterpret_cast<float2*>(Cout + (size_t)(r + 8) * Nout + n) = o1;
        }
    }
}

// ------- top-k with banded exact repair + fused hidden (1 limb) -----------
__device__ __forceinline__ uint32_t fmap(float f) {
    uint32_t b = __float_as_uint(f);
    return (b & 0x80000000u) ? ~b : (b | 0x80000000u);
}
__device__ __forceinline__ float funmap(uint32_t u) {
    uint32_t bits = (u & 0x80000000u) ? (u ^ 0x80000000u) : ~u;
    return __uint_as_float(bits);
}
__global__ void k_topk_repair(const float* __restrict__ x,
                              const float* __restrict__ b_syn) {
    __shared__ uint32_t srow[NN];
    __shared__ float    xs[DD];
    __shared__ uint32_t hist[256];
    __shared__ double   bz[BANDCAP];
    __shared__ int      bidx[BANDCAP];
    __shared__ unsigned char binc[BANDCAP];
    __shared__ uint32_t s_prefix, s_kk;
    __shared__ int      s_A, s_cnt;
    const int row = blockIdx.x, tid = threadIdx.x;
    const int warp = tid >> 5, lane = tid & 31;

    const uint4* zp = reinterpret_cast<const uint4*>(g_Z + (size_t)row * NN);
    for (int i = tid; i < NN / 4; i += 256) {
        uint4 v = zp[i];
        srow[i * 4 + 0] = fmap(__uint_as_float(v.x));
        srow[i * 4 + 1] = fmap(__uint_as_float(v.y));
        srow[i * 4 + 2] = fmap(__uint_as_float(v.z));
        srow[i * 4 + 3] = fmap(__uint_as_float(v.w));
    }
    for (int i = tid; i < DD; i += 256) xs[i] = x[(size_t)row * DD + i];
    if (tid == 0) { s_prefix = 0u; s_kk = TOPK; s_A = 0; s_cnt = 0; }
    __syncthreads();

    uint32_t maskhi = 0u;
    for (int b = 3; b >= 0; b--) {
        hist[tid] = 0u;
        __syncthreads();
        const uint32_t pref = s_prefix;
        const int sh = 8 * b;
        for (int i = tid; i < NN; i += 256) {
            uint32_t u = srow[i];
            if ((u & maskhi) == pref) atomicAdd(&hist[(u >> sh) & 0xFF], 1u);
        }
        __syncthreads();
        if (tid == 0) {
            uint32_t cum = 0, kk = s_kk; int sel = 0;
            for (int v = 255; v >= 0; v--) {
                uint32_t c = hist[v];
                if (cum + c >= kk) { sel = v; s_kk = kk - cum; break; }
                cum += c;
            }
            s_prefix = pref | ((uint32_t)sel << sh);
        }
        __syncthreads();
        maskhi |= (0xFFu << (8 * b));
    }
    const float th2 = funmap(s_prefix);
    const float thhi = th2 + 3e-3f;
    const float thlo = th2 - 3e-3f;

    for (int i = tid; i < NN; i += 256) {
        float z = funmap(srow[i]);
        if (z > thhi) atomicAdd(&s_A, 1);
        else if (z >= thlo) {
            int p = atomicAdd(&s_cnt, 1);
            if (p < BANDCAP) bidx[p] = i;
        }
    }
    __syncthreads();
    const int cnt = min(s_cnt, BANDCAP);
    const int need = TOPK - s_A;

    const double sc = (double)g_scale[0];
    for (int b = warp; b < cnt; b += 8) {
        const int j = bidx[b];
        const u16* q = g_Q1 + (size_t)j * DD;
        double acc = 0.0;
        for (int k = lane; k < DD; k += 32)
            acc += (double)xs[k] * (double)__bfloat162float(__ushort_as_bfloat16(q[k]));
#pragma unroll
        for (int o = 16; o > 0; o >>= 1) acc += __shfl_down_sync(0xffffffffu, acc, o);
        if (lane == 0) bz[b] = acc * sc + (double)b_syn[j];
    }
    __syncthreads();

    for (int b = tid; b < cnt; b += 256) {
        int rank = 0;
        double v = bz[b];
        for (int b2 = 0; b2 < cnt; b2++) rank += (bz[b2] > v);
        binc[b] = (rank < need) ? 1 : 0;
    }
    __syncthreads();

    u16* hrow = g_H1 + (size_t)row * NN;
    for (int i = tid; i < NN / 4; i += 256) {
        ushort4 p;
        u16* a = &p.x;
#pragma unroll
        for (int j = 0; j < 4; j++) {
            float z = funmap(srow[i * 4 + j]);
            float h = (z > thhi) ? fmaxf(z, 0.0f) : 0.0f;
            a[j] = __bfloat16_as_ushort(__float2bfloat16_rn(h));
        }
        reinterpret_cast<ushort4*>(hrow)[i] = p;
    }
    __syncthreads();
    for (int b = tid; b < cnt; b += 256) {
        int j = bidx[b];
        float z = funmap(srow[j]);
        float h = binc[b] ? fmaxf(z, 0.0f) : 0.0f;
        hrow[j] = __bfloat16_as_ushort(__float2bfloat16_rn(h));
    }
}

__global__ void k_ln(const float* __restrict__ gamma, const float* __restrict__ beta,
                     float* __restrict__ out) {
    __shared__ float ssum[256], ssq[256];
    const int row = blockIdx.x, t = threadIdx.x;
    const float4* xp = reinterpret_cast<const float4*>(g_XO + (size_t)row * DD);
    float4 v0 = xp[t], v1 = xp[t + 256];
    float s = v0.x + v0.y + v0.z + v0.w + v1.x + v1.y + v1.z + v1.w;
    float q = v0.x * v0.x + v0.y * v0.y + v0.z * v0.z + v0.w * v0.w +
              v1.x * v1.x + v1.y * v1.y + v1.z * v1.z + v1.w * v1.w;
    ssum[t] = s; ssq[t] = q; __syncthreads();
    for (int o = 128; o > 0; o >>= 1) {
        if (t < o) { ssum[t] += ssum[t + o]; ssq[t] += ssq[t + o]; }
        __syncthreads();
    }
    float mu  = ssum[0] * (1.0f / DD);
    float var = ssq[0] * (1.0f / DD) - mu * mu;
    float rs  = rsqrtf(var + 1e-5f);
    const float4* gp = reinterpret_cast<const float4*>(gamma);
    const float4* bp = reinterpret_cast<const float4*>(beta);
    float4 g0 = gp[t], g1 = gp[t + 256];
    float4 b0 = bp[t], b1 = bp[t + 256];
    float4 o0, o1;
    o0.x = (v0.x - mu) * rs * g0.x + b0.x; o0.y = (v0.y - mu) * rs * g0.y + b0.y;
    o0.z = (v0.z - mu) * rs * g0.z + b0.z; o0.w = (v0.w - mu) * rs * g0.w + b0.w;
    o1.x = (v1.x - mu) * rs * g1.x + b1.x; o1.y = (v1.y - mu) * rs * g1.y + b1.y;
    o1.z = (v1.z - mu) * rs * g1.z + b1.z; o1.w = (v1.w - mu) * rs * g1.w + b1.w;
    float4* op = reinterpret_cast<float4*>(out + (size_t)row * DD);
    op[t] = o0; op[t + 256] = o1;
}

// ---------------- launcher --------------------------------------------------
extern "C" void kernel_launch(void* const* d_in, const int* in_sizes, int n_in,
                              void* d_out, int out_size) {
    (void)in_sizes; (void)n_in; (void)out_size;
    const float* x     = (const float*)d_in[0];
    const float* W_syn = (const float*)d_in[1];
    const float* b_syn = (const float*)d_in[2];
    const float* W_out = (const float*)d_in[3];
    const float* b_out = (const float*)d_in[4];
    const float* gamma = (const float*)d_in[5];
    const float* beta  = (const float*)d_in[6];
    float* out = (float*)d_out;

    const int SM1 = 3 * (2 * 18432 + 36864);   // 221184 B
    const int SM2 = 3 * (1 * 18432 + 36864);   // 165888 B
    cudaFuncSetAttribute(k_gemm_hmma<0, 2>, cudaFuncAttributeMaxDynamicSharedMemorySize, SM1);
    cudaFuncSetAttribute(k_gemm_hmma<1, 1>, cudaFuncAttributeMaxDynamicSharedMemorySize, SM2);

    // 3 launches before GEMM1 -> GEMM1 is global launch #6 (2 harness kernels
    // precede ours) -> ncu -s 5 -c 1 captures the GEMM.
    k_abs2<<<dim3(2048, 2), 256>>>(W_syn, W_out);
    k_finalize_scales<<<1, 256>>>();
    k_prep<<<49152, 256>>>((const float4*)W_syn, (const float4*)W_out, (const float4*)x);
    k_gemm_hmma<0, 2><<<dim3(32, 64), 256, SM1>>>(b_syn, nullptr);
    k_topk_repair<<<MM, 256>>>(x, b_syn);
    k_gemm_hmma<1, 1><<<dim3(8, 64), 256, SM2>>>(b_out, x);
    k_ln<<<MM, 256>>>(gamma, beta, out);
}

// round 13
// speedup vs baseline: 2.6020x; 1.0008x over previous
#include <cuda_runtime.h>
#include <cuda_bf16.h>
#include <cstdint>

#define MM 8192
#define DD 2048
#define NN 8192
#define TOPK 819
#define BANDCAP 192
typedef unsigned short u16;

__device__ double g_partial[4096];
__device__ float  g_scale[2];
__device__ __align__(16) u16   g_X1[(size_t)MM * DD];
__device__ __align__(16) u16   g_X2[(size_t)MM * DD];
__device__ __align__(16) u16   g_Q1[(size_t)NN * DD];
__device__ __align__(16) u16   g_Q2[(size_t)DD * NN];
__device__ __align__(16) float g_Z [(size_t)MM * NN];
__device__ __align__(16) u16   g_H1[(size_t)MM * NN];
__device__ __align__(16) float g_XO[(size_t)MM * DD];

__device__ __forceinline__ uint32_t smem_u32(const void* p) {
    uint32_t a;
    asm("{ .reg .u64 t; cvta.to.shared.u64 t, %1; cvt.u32.u64 %0, t; }" : "=r"(a) : "l"(p));
    return a;
}
#define CP_COMMIT() asm volatile("cp.async.commit_group;" ::: "memory")
#define CP_WAIT(n)  asm volatile("cp.async.wait_group %0;" :: "n"(n) : "memory")

__device__ __forceinline__ void ldsm4(uint32_t* r, uint32_t addr) {
    asm volatile("ldmatrix.sync.aligned.m8n8.x4.shared.b16 {%0,%1,%2,%3}, [%4];"
                 : "=r"(r[0]), "=r"(r[1]), "=r"(r[2]), "=r"(r[3]) : "r"(addr));
}
__device__ __forceinline__ void mma16816(float* c, uint32_t a0, uint32_t a1,
                                         uint32_t a2, uint32_t a3,
                                         uint32_t b0, uint32_t b1) {
    asm volatile(
        "mma.sync.aligned.m16n8k16.row.col.f32.bf16.bf16.f32 "
        "{%0,%1,%2,%3}, {%4,%5,%6,%7}, {%8,%9}, {%0,%1,%2,%3};\n"
        : "+f"(c[0]), "+f"(c[1]), "+f"(c[2]), "+f"(c[3])
        : "r"(a0), "r"(a1), "r"(a2), "r"(a3), "r"(b0), "r"(b1));
}

// ---------------- prep (exactly 3 launches before GEMM1) -------------------
__global__ void k_abs2(const float* __restrict__ Wa, const float* __restrict__ Wb) {
    __shared__ double sd[256];
    const int which = blockIdx.y;
    const float* W = which ? Wb : Wa;
    size_t base = (size_t)blockIdx.x * 8192 + threadIdx.x;
    double s = 0.0;
#pragma unroll
    for (int i = 0; i < 32; i++) s += (double)fabsf(W[base + (size_t)i * 256]);
    sd[threadIdx.x] = s; __syncthreads();
    for (int o = 128; o > 0; o >>= 1) {
        if ((int)threadIdx.x < o) sd[threadIdx.x] += sd[threadIdx.x + o];
        __syncthreads();
    }
    if (threadIdx.x == 0) g_partial[which * 2048 + blockIdx.x] = sd[0];
}
__global__ void k_finalize_scales() {
    __shared__ double sd[256];
    for (int w = 0; w < 2; w++) {
        double s = 0.0;
        for (int i = threadIdx.x; i < 2048; i += 256) s += g_partial[w * 2048 + i];
        sd[threadIdx.x] = s; __syncthreads();
        for (int o = 128; o > 0; o >>= 1) {
            if ((int)threadIdx.x < o) sd[threadIdx.x] += sd[threadIdx.x + o];
            __syncthreads();
        }
        if (threadIdx.x == 0) g_scale[w] = (float)(sd[0] / 16777216.0);
        __syncthreads();
    }
}
__device__ __forceinline__ u16 tq1(float w, float den) {
    float t = __fdiv_rn(w, den);
    float q = fmaxf(-1.0f, fminf(1.0f, rintf(t)));
    return __bfloat16_as_ushort(__float2bfloat16_rn(q));
}
__global__ void k_prep(const float4* __restrict__ Wa, const float4* __restrict__ Wb,
                       const float4* __restrict__ x) {
    const int part = blockIdx.x >> 14;
    size_t i = ((size_t)(blockIdx.x & 16383)) * 256 + threadIdx.x;
    if (part < 2) {
        const float4* W = part ? Wb : Wa;
        float den = g_scale[part] + 1e-8f;
        float4 w = W[i];
        ushort4 q;
        q.x = tq1(w.x, den); q.y = tq1(w.y, den); q.z = tq1(w.z, den); q.w = tq1(w.w, den);
        reinterpret_cast<ushort4*>(part ? g_Q2 : g_Q1)[i] = q;
    } else {
        float4 v = x[i];
        float f[4] = {v.x, v.y, v.z, v.w};
        ushort4 p1, p2;
        u16* a1 = &p1.x; u16* a2 = &p2.x;
#pragma unroll
        for (int j = 0; j < 4; j++) {
            __nv_bfloat16 b1 = __float2bfloat16_rn(f[j]);
            float r1 = f[j] - __bfloat162float(b1);
            a1[j] = __bfloat16_as_ushort(b1);
            a2[j] = __bfloat16_as_ushort(__float2bfloat16_rn(r1));
        }
        reinterpret_cast<ushort4*>(g_X1)[i] = p1;
        reinterpret_cast<ushort4*>(g_X2)[i] = p2;
    }
}

// ---------------- pipelined HMMA GEMM, k-step 64, 512 threads ---------------
// CTA 128(m) x 256(n), 16 warps (4m x 4n), warp tile 32x64, k-step 64,
// 3-stage cp.async. smem rows: 128B data + 16B pad = 144B pitch
// (16x9 -> ldmatrix 8-row phases hit 8 distinct banks).
template<int GID, int NLIMB>
__global__ void __launch_bounds__(512) k_gemm_hmma(
    const float* __restrict__ bias, const float* __restrict__ xres) {
    constexpr int AT = 128 * 144;             // 18432
    constexpr int BT = 256 * 144;             // 36864
    constexpr int STAGE = NLIMB * AT + BT;
    constexpr int Kdim = (GID == 0) ? DD : NN;
    constexpr int Nout = (GID == 0) ? NN : DD;
    constexpr int steps = Kdim >> 6;

    extern __shared__ char sm[];
    const uint32_t smaddr = smem_u32(sm);
    const int tid = threadIdx.x;
    const int warp = tid >> 5, lane = tid & 31;
    const int wm = warp >> 2, wn = warp & 3;
    const int tr = lane >> 2, tc = lane & 3;
    const int m0 = blockIdx.y * 128, n0 = blockIdx.x * 256;

    const u16* At[2];
    if (GID == 0) { At[0] = g_X1; At[1] = g_X2; }
    else          { At[0] = g_H1; At[1] = g_H1; }
    const u16* Bq = (GID == 0) ? g_Q1 : g_Q2;
    float* Cout = (GID == 0) ? g_Z : g_XO;

    float acc[2][8][4];
#pragma unroll
    for (int a = 0; a < 2; a++)
#pragma unroll
        for (int b = 0; b < 8; b++)
#pragma unroll
            for (int c = 0; c < 4; c++) acc[a][b][c] = 0.0f;

    const uint32_t aoff = (uint32_t)((wm * 32 + (lane & 15)) * 144 + ((lane & 16) ? 16 : 0));
    const uint32_t boff = (uint32_t)((wn * 64 + (lane & 7) + ((lane & 16) ? 8 : 0)) * 144 +
                                     ((lane & 8) ? 16 : 0));

    // one stage = NLIMB A tiles (128 rows x 128B) + B tile (256 rows x 128B)
#define LOAD_STAGE(stbuf, kkelem)                                                     \
    do {                                                                              \
        _Pragma("unroll")                                                             \
        for (int l = 0; l < NLIMB; l++) {                                             \
            _Pragma("unroll")                                                         \
            for (int j = 0; j < 2; j++) {                                             \
                int c = tid + 512 * j;                                                \
                int row = c >> 3, col = (c & 7) * 16;                                 \
                uint32_t dst = smaddr + (stbuf) * STAGE + l * AT + row * 144 + col;   \
                const char* src = (const char*)(At[l] + (size_t)(m0 + row) * Kdim + (kkelem)) + col; \
                asm volatile("cp.async.cg.shared.global [%0], [%1], 16;" :: "r"(dst), "l"(src) : "memory"); \
            }                                                                         \
        }                                                                             \
        _Pragma("unroll")                                                             \
        for (int j = 0; j < 4; j++) {                                                 \
            int c = tid + 512 * j;                                                    \
            int row = c >> 3, col = (c & 7) * 16;                                     \
            uint32_t dst = smaddr + (stbuf) * STAGE + NLIMB * AT + row * 144 + col;   \
            const char* src = (const char*)(Bq + (size_t)(n0 + row) * Kdim + (kkelem)) + col; \
            asm volatile("cp.async.cg.shared.global [%0], [%1], 16;" :: "r"(dst), "l"(src) : "memory"); \
        }                                                                             \
    } while (0)

#pragma unroll
    for (int st = 0; st < 2; st++) {
        LOAD_STAGE(st, st * 64);
        CP_COMMIT();
    }

    for (int t = 0; t < steps; t++) {
        CP_WAIT(1);
        __syncthreads();
        if (t + 2 < steps) {
            const int st = (t + 2) % 3;
            LOAD_STAGE(st, (t + 2) * 64);
        }
        CP_COMMIT();

        const uint32_t sstage = smaddr + (t % 3) * STAGE;
        const uint32_t sB = sstage + NLIMB * AT;
#pragma unroll
        for (int h = 0; h < 4; h++) {
            uint32_t breg[4][4];
#pragma unroll
            for (int nb = 0; nb < 4; nb++)
                ldsm4(breg[nb], sB + boff + nb * 2304 + h * 32);
#pragma unroll
            for (int l = 0; l < NLIMB; l++) {
                uint32_t areg[2][4];
#pragma unroll
                for (int mt = 0; mt < 2; mt++)
                    ldsm4(areg[mt], sstage + l * AT + aoff + mt * 2304 + h * 32);
#pragma unroll
                for (int mt = 0; mt < 2; mt++)
#pragma unroll
                    for (int nt = 0; nt < 8; nt++)
                        mma16816(acc[mt][nt], areg[mt][0], areg[mt][1], areg[mt][2], areg[mt][3],
                                 breg[nt >> 1][(nt & 1) * 2], breg[nt >> 1][(nt & 1) * 2 + 1]);
            }
        }
    }
#undef LOAD_STAGE

    const float sc = g_scale[GID];
#pragma unroll
    for (int mt = 0; mt < 2; mt++) {
        int r = m0 + wm * 32 + mt * 16 + tr;
#pragma unroll
        for (int nt = 0; nt < 8; nt++) {
            int n = n0 + wn * 64 + nt * 8 + tc * 2;
            float2 bs = *reinterpret_cast<const float2*>(bias + n);
            float2 o0 = make_float2(fmaf(acc[mt][nt][0], sc, bs.x),
                                    fmaf(acc[mt][nt][1], sc, bs.y));
            float2 o1 = make_float2(fmaf(acc[mt][nt][2], sc, bs.x),
                                    fmaf(acc[mt][nt][3], sc, bs.y));
            if (GID == 1) {
                float2 x0 = *reinterpret_cast<const float2*>(xres + (size_t)r * Nout + n);
                float2 x1 = *reinterpret_cast<const float2*>(xres + (size_t)(r + 8) * Nout + n);
                o0.x += x0.x; o0.y += x0.y; o1.x += x1.x; o1.y += x1.y;
            }
            *reinterpret_cast<float2*>(Cout + (size_t)r * Nout + n)       = o0;
            *reinterpret_cast<float2*>(Cout + (size_t)(r + 8) * Nout + n) = o1;
        }
    }
}

// ------- top-k with banded exact repair + fused hidden (1 limb) -----------
__device__ __forceinline__ uint32_t fmap(float f) {
    uint32_t b = __float_as_uint(f);
    return (b & 0x80000000u) ? ~b : (b | 0x80000000u);
}
__device__ __forceinline__ float funmap(uint32_t u) {
    uint32_t bits = (u & 0x80000000u) ? (u ^ 0x80000000u) : ~u;
    return __uint_as_float(bits);
}
__global__ void k_topk_repair(const float* __restrict__ x,
                              const float* __restrict__ b_syn) {
    __shared__ uint32_t srow[NN];
    __shared__ float    xs[DD];
    __shared__ uint32_t hist[256];
    __shared__ double   bz[BANDCAP];
    __shared__ int      bidx[BANDCAP];
    __shared__ unsigned char binc[BANDCAP];
    __shared__ uint32_t s_prefix, s_kk;
    __shared__ int      s_A, s_cnt;
    const int row = blockIdx.x, tid = threadIdx.x;
    const int warp = tid >> 5, lane = tid & 31;

    const uint4* zp = reinterpret_cast<const uint4*>(g_Z + (size_t)row * NN);
    for (int i = tid; i < NN / 4; i += 256) {
        uint4 v = zp[i];
        srow[i * 4 + 0] = fmap(__uint_as_float(v.x));
        srow[i * 4 + 1] = fmap(__uint_as_float(v.y));
        srow[i * 4 + 2] = fmap(__uint_as_float(v.z));
        srow[i * 4 + 3] = fmap(__uint_as_float(v.w));
    }
    for (int i = tid; i < DD; i += 256) xs[i] = x[(size_t)row * DD + i];
    if (tid == 0) { s_prefix = 0u; s_kk = TOPK; s_A = 0; s_cnt = 0; }
    __syncthreads();

    uint32_t maskhi = 0u;
    for (int b = 3; b >= 0; b--) {
        hist[tid] = 0u;
        __syncthreads();
        const uint32_t pref = s_prefix;
        const int sh = 8 * b;
        for (int i = tid; i < NN; i += 256) {
            uint32_t u = srow[i];
            if ((u & maskhi) == pref) atomicAdd(&hist[(u >> sh) & 0xFF], 1u);
        }
        __syncthreads();
        if (tid == 0) {
            uint32_t cum = 0, kk = s_kk; int sel = 0;
            for (int v = 255; v >= 0; v--) {
                uint32_t c = hist[v];
                if (cum + c >= kk) { sel = v; s_kk = kk - cum; break; }
                cum += c;
            }
            s_prefix = pref | ((uint32_t)sel << sh);
        }
        __syncthreads();
        maskhi |= (0xFFu << (8 * b));
    }
    const float th2 = funmap(s_prefix);
    const float thhi = th2 + 3e-3f;
    const float thlo = th2 - 3e-3f;

    for (int i = tid; i < NN; i += 256) {
        float z = funmap(srow[i]);
        if (z > thhi) atomicAdd(&s_A, 1);
        else if (z >= thlo) {
            int p = atomicAdd(&s_cnt, 1);
            if (p < BANDCAP) bidx[p] = i;
        }
    }
    __syncthreads();
    const int cnt = min(s_cnt, BANDCAP);
    const int need = TOPK - s_A;

    const double sc = (double)g_scale[0];
    for (int b = warp; b < cnt; b += 8) {
        const int j = bidx[b];
        const u16* q = g_Q1 + (size_t)j * DD;
        double acc = 0.0;
        for (int k = lane; k < DD; k += 32)
            acc += (double)xs[k] * (double)__bfloat162float(__ushort_as_bfloat16(q[k]));
#pragma unroll
        for (int o = 16; o > 0; o >>= 1) acc += __shfl_down_sync(0xffffffffu, acc, o);
        if (lane == 0) bz[b] = acc * sc + (double)b_syn[j];
    }
    __syncthreads();

    for (int b = tid; b < cnt; b += 256) {
        int rank = 0;
        double v = bz[b];
        for (int b2 = 0; b2 < cnt; b2++) rank += (bz[b2] > v);
        binc[b] = (rank < need) ? 1 : 0;
    }
    __syncthreads();

    u16* hrow = g_H1 + (size_t)row * NN;
    for (int i = tid; i < NN / 4; i += 256) {
        ushort4 p;
        u16* a = &p.x;
#pragma unroll
        for (int j = 0; j < 4; j++) {
            float z = funmap(srow[i * 4 + j]);
            float h = (z > thhi) ? fmaxf(z, 0.0f) : 0.0f;
            a[j] = __bfloat16_as_ushort(__float2bfloat16_rn(h));
        }
        reinterpret_cast<ushort4*>(hrow)[i] = p;
    }
    __syncthreads();
    for (int b = tid; b < cnt; b += 256) {
        int j = bidx[b];
        float z = funmap(srow[j]);
        float h = binc[b] ? fmaxf(z, 0.0f) : 0.0f;
        hrow[j] = __bfloat16_as_ushort(__float2bfloat16_rn(h));
    }
}

__global__ void k_ln(const float* __restrict__ gamma, const float* __restrict__ beta,
                     float* __restrict__ out) {
    __shared__ float ssum[256], ssq[256];
    const int row = blockIdx.x, t = threadIdx.x;
    const float4* xp = reinterpret_cast<const float4*>(g_XO + (size_t)row * DD);
    float4 v0 = xp[t], v1 = xp[t + 256];
    float s = v0.x + v0.y + v0.z + v0.w + v1.x + v1.y + v1.z + v1.w;
    float q = v0.x * v0.x + v0.y * v0.y + v0.z * v0.z + v0.w * v0.w +
              v1.x * v1.x + v1.y * v1.y + v1.z * v1.z + v1.w * v1.w;
    ssum[t] = s; ssq[t] = q; __syncthreads();
    for (int o = 128; o > 0; o >>= 1) {
        if (t < o) { ssum[t] += ssum[t + o]; ssq[t] += ssq[t + o]; }
        __syncthreads();
    }
    float mu  = ssum[0] * (1.0f / DD);
    float var = ssq[0] * (1.0f / DD) - mu * mu;
    float rs  = rsqrtf(var + 1e-5f);
    const float4* gp = reinterpret_cast<const float4*>(gamma);
    const float4* bp = reinterpret_cast<const float4*>(beta);
    float4 g0 = gp[t], g1 = gp[t + 256];
    float4 b0 = bp[t], b1 = bp[t + 256];
    float4 o0, o1;
    o0.x = (v0.x - mu) * rs * g0.x + b0.x; o0.y = (v0.y - mu) * rs * g0.y + b0.y;
    o0.z = (v0.z - mu) * rs * g0.z + b0.z; o0.w = (v0.w - mu) * rs * g0.w + b0.w;
    o1.x = (v1.x - mu) * rs * g1.x + b1.x; o1.y = (v1.y - mu) * rs * g1.y + b1.y;
    o1.z = (v1.z - mu) * rs * g1.z + b1.z; o1.w = (v1.w - mu) * rs * g1.w + b1.w;
    float4* op = reinterpret_cast<float4*>(out + (size_t)row * DD);
    op[t] = o0; op[t + 256] = o1;
}

// ---------------- launcher --------------------------------------------------
extern "C" void kernel_launch(void* const* d_in, const int* in_sizes, int n_in,
                              void* d_out, int out_size) {
    (void)in_sizes; (void)n_in; (void)out_size;
    const float* x     = (const float*)d_in[0];
    const float* W_syn = (const float*)d_in[1];
    const float* b_syn = (const float*)d_in[2];
    const float* W_out = (const float*)d_in[3];
    const float* b_out = (const float*)d_in[4];
    const float* gamma = (const float*)d_in[5];
    const float* beta  = (const float*)d_in[6];
    float* out = (float*)d_out;

    const int SM1 = 3 * (2 * 18432 + 36864);   // 221184 B
    const int SM2 = 3 * (1 * 18432 + 36864);   // 165888 B
    cudaFuncSetAttribute(k_gemm_hmma<0, 2>, cudaFuncAttributeMaxDynamicSharedMemorySize, SM1);
    cudaFuncSetAttribute(k_gemm_hmma<1, 1>, cudaFuncAttributeMaxDynamicSharedMemorySize, SM2);

    // 3 launches before GEMM1 -> ncu -s 5 -c 1 keeps capturing the GEMM.
    k_abs2<<<dim3(2048, 2), 256>>>(W_syn, W_out);
    k_finalize_scales<<<1, 256>>>();
    k_prep<<<49152, 256>>>((const float4*)W_syn, (const float4*)W_out, (const float4*)x);
    k_gemm_hmma<0, 2><<<dim3(32, 64), 512, SM1>>>(b_syn, nullptr);
    k_topk_repair<<<MM, 256>>>(x, b_syn);
    k_gemm_hmma<1, 1><<<dim3(8, 64), 512, SM2>>>(b_out, x);
    k_ln<<<MM, 256>>>(gamma, beta, out);
}